// round 14
// baseline (speedup 1.0000x reference)
#include <cuda_runtime.h>
#include <cstdint>

// Psi11t flow force: F = 2*t*c0 * ( s x (Fs*b + Fbs) )
//   Fs = nbr4(s), b = s.Fs, Fbs = nbr4(s*b). Periodic 512x512, B=32, S=3.
// R13 body (cp.async 6-slot ring, 2 rows/iter, 1 barrier, distributed-b
// algebra) + BALANCED WAVE: exactly 592 = 148x4 blocks, each owning an equal
// share (13/14 pairs) of the 8192 global row-pairs; runs split at batch
// boundaries (always even-length).

#define MASK 511
#define NTH 128
#define NSLOT 6

__device__ __forceinline__ float4 operator+(float4 a, float4 b) {
    return make_float4(a.x + b.x, a.y + b.y, a.z + b.z, a.w + b.w);
}
__device__ __forceinline__ float4 fma4(float4 a, float4 b, float4 c) {
    return make_float4(fmaf(a.x, b.x, c.x), fmaf(a.y, b.y, c.y),
                       fmaf(a.z, b.z, c.z), fmaf(a.w, b.w, c.w));
}
__device__ __forceinline__ float4 mul4(float4 a, float4 b) {
    return make_float4(a.x * b.x, a.y * b.y, a.z * b.z, a.w * b.w);
}
__device__ __forceinline__ float4 crossm(float4 a, float4 b, float4 c, float4 d) {
    return make_float4(fmaf(a.x, b.x, -(c.x * d.x)), fmaf(a.y, b.y, -(c.y * d.y)),
                       fmaf(a.z, b.z, -(c.z * d.z)), fmaf(a.w, b.w, -(c.w * d.w)));
}
__device__ __forceinline__ float4 ymv(float4 a, float lw) {
    return make_float4(lw, a.x, a.y, a.z);
}
__device__ __forceinline__ float4 ypv(float4 a, float rx) {
    return make_float4(a.y, a.z, a.w, rx);
}
__device__ __forceinline__ float4 scale4(float k, float4 a) {
    return make_float4(k * a.x, k * a.y, k * a.z, k * a.w);
}
__device__ __forceinline__ void cpa16(float* smem_dst, const float* g) {
    uint32_t sa = (uint32_t)__cvta_generic_to_shared(smem_dst);
    asm volatile("cp.async.cg.shared.global [%0], [%1], 16;" :: "r"(sa), "l"(g));
}
__device__ __forceinline__ void cpa_commit() {
    asm volatile("cp.async.commit_group;");
}
__device__ __forceinline__ void cpa_wait1() {
    asm volatile("cp.async.wait_group 1;");
}
__device__ __forceinline__ void cpa_wait0() {
    asm volatile("cp.async.wait_group 0;");
}

__global__ __launch_bounds__(NTH, 4) void psi11t_kernel(
    const float* __restrict__ s,
    const float* __restrict__ tt,
    const float* __restrict__ c0,
    float* __restrict__ out)
{
    __shared__ float ring[NSLOT][3][512];   // 36864 B
    __shared__ float bw[2][NTH], bx[2][NTH];

    const int t  = threadIdx.x;
    const int tm = (t - 1) & (NTH - 1);
    const int tp = (t + 1) & (NTH - 1);
    const int yo  = 4 * t;
    const int ym1 = (yo - 1) & MASK;
    const int ym2 = (yo - 2) & MASK;
    const int yp4 = (yo + 4) & MASK;
    const int yp5 = (yo + 5) & MASK;

    const float coeff = 2.0f * tt[0] * c0[0];

    // Balanced share: 8192 row-pairs over 592 blocks -> 496 blocks x14 + 96 x13
    const int bid = blockIdx.x;
    const int extra = (bid < 496) ? bid : 496;
    const int sp = bid * 13 + extra;
    const int np = 13 + (bid < 496 ? 1 : 0);
    int g0 = sp * 2;
    const int g1 = g0 + np * 2;

    while (g0 < g1) {
        __syncthreads();   // ring/bounds reuse across runs

        const int bb = g0 >> 9;
        const int xs = g0 & MASK;
        const int nrows = min(g1 - g0, 512 - xs);
        const int n2 = nrows >> 1;
        const long base = (long)bb * (3L << 18);
        const float* sb = s + base;

        // ---- run prefetch: rows xs+2, xs+3 as ONE group ----
        {
            const int r2 = (xs + 2) & MASK, r3 = (xs + 3) & MASK;
            #pragma unroll
            for (int c = 0; c < 3; ++c) {
                cpa16(&ring[(xs + 2) % NSLOT][c][yo], sb + ((long)c << 18) + ((long)r2 << 9) + yo);
                cpa16(&ring[(xs + 3) % NSLOT][c][yo], sb + ((long)c << 18) + ((long)r3 << 9) + yo);
            }
            cpa_commit();
        }

        // Persistent per-run state
        float4 sP[3], sC[3], sN[3];
        float4 bP, bC;
        float  sClw[3], sCrx[3], sNlw[3], sNrx[3];
        float  bClw, bCrx;

        // ---- run prologue: rows xs-2 .. xs+1 (direct LDG) ----
        {
            const int rA = (xs - 2) & MASK, rP = (xs - 1) & MASK;
            const int rC = xs, rN = (xs + 1) & MASK;
            float4 sA[3];
            float plw[3], prx[3];
            #pragma unroll
            for (int c = 0; c < 3; ++c) {
                const float* cp = sb + ((long)c << 18);
                sA[c] = *(const float4*)(cp + ((long)rA << 9) + yo);
                sP[c] = *(const float4*)(cp + ((long)rP << 9) + yo);
                sC[c] = *(const float4*)(cp + ((long)rC << 9) + yo);
                sN[c] = *(const float4*)(cp + ((long)rN << 9) + yo);
                plw[c]  = cp[((long)rP << 9) + ym1];  prx[c]  = cp[((long)rP << 9) + yp4];
                sClw[c] = cp[((long)rC << 9) + ym1];  sCrx[c] = cp[((long)rC << 9) + yp4];
                sNlw[c] = cp[((long)rN << 9) + ym1];  sNrx[c] = cp[((long)rN << 9) + yp4];
            }

            bP = make_float4(0.f, 0.f, 0.f, 0.f);
            #pragma unroll
            for (int c = 0; c < 3; ++c)
                bP = fma4(sP[c], sA[c] + sC[c] + ymv(sP[c], plw[c]) + ypv(sP[c], prx[c]), bP);
            bP = scale4(coeff, bP);

            bC = make_float4(0.f, 0.f, 0.f, 0.f);
            #pragma unroll
            for (int c = 0; c < 3; ++c)
                bC = fma4(sC[c], sP[c] + sN[c] + ymv(sC[c], sClw[c]) + ypv(sC[c], sCrx[c]), bC);
            bC = scale4(coeff, bC);

            bw[1][t] = bC.w; bx[1][t] = bC.x;
            __syncthreads();
            bClw = bw[1][tm]; bCrx = bx[1][tp];
        }

        // ---- run main loop: 2 rows per iteration ----
        #pragma unroll 2
        for (int i = 0; i < n2; ++i) {
            const int x = xs + 2 * i;
            const int p = i & 1;
            const int s2 = (x + 2) % NSLOT, s3 = (x + 3) % NSLOT;

            // 1. prefetch rows x+4, x+5 unless this is the last pair
            if (i + 1 < n2) {
                const int r4 = (x + 4) & MASK, r5 = (x + 5) & MASK;
                #pragma unroll
                for (int c = 0; c < 3; ++c) {
                    cpa16(&ring[(x + 4) % NSLOT][c][yo], sb + ((long)c << 18) + ((long)r4 << 9) + yo);
                    cpa16(&ring[(x + 5) % NSLOT][c][yo], sb + ((long)c << 18) + ((long)r5 << 9) + yo);
                }
                cpa_commit();
                cpa_wait1();
            } else {
                cpa_wait0();
            }

            float4 sN2[3], sN3[3];
            #pragma unroll
            for (int c = 0; c < 3; ++c) {
                sN2[c] = *(const float4*)&ring[s2][c][yo];
                sN3[c] = *(const float4*)&ring[s3][c][yo];
            }

            // 3. bN = coeff * b(x+1)
            float4 bN = make_float4(0.f, 0.f, 0.f, 0.f);
            #pragma unroll
            for (int c = 0; c < 3; ++c)
                bN = fma4(sN[c], sC[c] + sN2[c] + ymv(sN[c], sNlw[c]) + ypv(sN[c], sNrx[c]), bN);
            bN = scale4(coeff, bN);

            // 4. publish bN bounds
            bw[p][t] = bN.w; bx[p][t] = bN.x;

            // 5. F(x)
            {
                const float4 wxm = bC + bP;
                const float4 wxp = bC + bN;
                const float4 wym = bC + ymv(bC, bClw);
                const float4 wyp = bC + ypv(bC, bCrx);
                float4 Fv[3];
                #pragma unroll
                for (int c = 0; c < 3; ++c) {
                    const float4 ymc = ymv(sC[c], sClw[c]);
                    const float4 ypc = ypv(sC[c], sCrx[c]);
                    Fv[c] = fma4(sP[c], wxm,
                            fma4(sN[c], wxp,
                            fma4(ymc, wym, mul4(ypc, wyp))));
                }
                float* op = out + base + (((long)x) << 9) + yo;
                __stcs((float4*)(op),              crossm(sC[1], Fv[2], sC[2], Fv[1]));
                __stcs((float4*)(op + (1L << 18)), crossm(sC[2], Fv[0], sC[0], Fv[2]));
                __stcs((float4*)(op + (2L << 18)), crossm(sC[0], Fv[1], sC[1], Fv[0]));
            }

            __syncthreads();

            // 6. post-barrier: bN bounds + ring halo; recompute bN2 edges
            const float bNlw = bw[p][tm], bNrx = bx[p][tp];
            float n2lw[3], n2rx[3], n3lw[3], n3rx[3];
            float bN2lw = 0.f, bN2rx = 0.f;
            #pragma unroll
            for (int c = 0; c < 3; ++c) {
                n2lw[c] = ring[s2][c][ym1];
                n2rx[c] = ring[s2][c][yp4];
                n3lw[c] = ring[s3][c][ym1];
                n3rx[c] = ring[s3][c][yp4];
                const float l2 = ring[s2][c][ym2];
                const float r5v = ring[s2][c][yp5];
                bN2lw = fmaf(n2lw[c], sNlw[c] + n3lw[c] + l2 + sN2[c].x, bN2lw);
                bN2rx = fmaf(n2rx[c], sNrx[c] + n3rx[c] + r5v + sN2[c].w, bN2rx);
            }
            bN2lw *= coeff; bN2rx *= coeff;

            // 7. bN2 = coeff * b(x+2)
            float4 bN2 = make_float4(0.f, 0.f, 0.f, 0.f);
            #pragma unroll
            for (int c = 0; c < 3; ++c)
                bN2 = fma4(sN2[c], sN[c] + sN3[c] + ymv(sN2[c], n2lw[c]) + ypv(sN2[c], n2rx[c]), bN2);
            bN2 = scale4(coeff, bN2);

            // 8. F(x+1)
            {
                const float4 wxm = bN + bC;
                const float4 wxp = bN + bN2;
                const float4 wym = bN + ymv(bN, bNlw);
                const float4 wyp = bN + ypv(bN, bNrx);
                float4 Fv[3];
                #pragma unroll
                for (int c = 0; c < 3; ++c) {
                    const float4 ymc = ymv(sN[c], sNlw[c]);
                    const float4 ypc = ypv(sN[c], sNrx[c]);
                    Fv[c] = fma4(sC[c], wxm,
                            fma4(sN2[c], wxp,
                            fma4(ymc, wym, mul4(ypc, wyp))));
                }
                float* op = out + base + (((long)(x + 1)) << 9) + yo;
                __stcs((float4*)(op),              crossm(sN[1], Fv[2], sN[2], Fv[1]));
                __stcs((float4*)(op + (1L << 18)), crossm(sN[2], Fv[0], sN[0], Fv[2]));
                __stcs((float4*)(op + (2L << 18)), crossm(sN[0], Fv[1], sN[1], Fv[0]));
            }

            // 9. rotate by 2 rows
            #pragma unroll
            for (int c = 0; c < 3; ++c) {
                sP[c] = sN[c]; sC[c] = sN2[c]; sN[c] = sN3[c];
                sClw[c] = n2lw[c]; sCrx[c] = n2rx[c];
                sNlw[c] = n3lw[c]; sNrx[c] = n3rx[c];
            }
            bP = bN; bC = bN2;
            bClw = bN2lw; bCrx = bN2rx;
        }

        g0 += nrows;
    }
}

extern "C" void kernel_launch(void* const* d_in, const int* in_sizes, int n_in,
                              void* d_out, int out_size)
{
    const float* s  = (const float*)d_in[0];
    const float* t  = (const float*)d_in[1];
    const float* c0 = (const float*)d_in[2];
    float* out = (float*)d_out;

    psi11t_kernel<<<592, NTH>>>(s, t, c0, out);   // 148 SMs x 4 blocks, one wave
}